// round 5
// baseline (speedup 1.0000x reference)
#include <cuda_runtime.h>
#include <math.h>

// Problem constants
#define B_   2
#define C_   512
#define HW_  32768          // H*W = 128*256
#define K_   19
#define GC_  4              // channels per block (1 per warp)
#define NCT_ (C_/GC_)       // 128 channel tiles
#define NCHUNK_ 8
#define PXC_ (HW_/NCHUNK_)  // 4096 pixels per chunk

// Scratch (no cudaMalloc allowed)
__device__ float d_scr[B_*NCHUNK_*2*C_*K_];   // 1.24 MB partial class sums
__device__ float d_dots[B_*2*K_*K_];          // Gram matrices
__device__ unsigned int d_ctr;                // arrival counter (reset each call)

// ---------------------------------------------------------------------------
// Kernel 1: segment sums, branch-free.
// lane = pixel, warp = channel. Each warp streams its channel row for BOTH
// tensors via float4 loads and scatters into private SMEM bins bins[k][lane]
// (float2 packs S,T). Bank index == lane -> conflict-free for any label.
// 2048 blocks of 128 threads -> ~11 blocks/SM resident (69% occ).
// ---------------------------------------------------------------------------
__global__ __launch_bounds__(128, 11) void seg_kernel(
    const float* __restrict__ S,
    const float* __restrict__ T,
    const int*   __restrict__ tgt)
{
    __shared__ float2 bins[GC_][K_*32];   // 4 warps x 19x32 float2 = 19.5 KB
    __shared__ float  outb[GC_][2][K_];

    int tid  = threadIdx.x;
    int lane = tid & 31;
    int warp = tid >> 5;

    int blk   = blockIdx.x;               // b*1024 + ct*8 + chunk
    int chunk = blk & (NCHUNK_ - 1);
    int ct    = (blk >> 3) & (NCT_ - 1);
    int b     = blk >> 10;
    int c     = ct * GC_ + warp;

    const float4* Sp = (const float4*)(S + ((size_t)(b*C_ + c))*HW_ + chunk*PXC_);
    const float4* Tp = (const float4*)(T + ((size_t)(b*C_ + c))*HW_ + chunk*PXC_);
    const int4*   Lp = (const int4*)(tgt + (size_t)b*HW_ + chunk*PXC_);

    float2* bin = bins[warp];
    for (int i = lane; i < K_*32; i += 32) bin[i] = make_float2(0.f, 0.f);
    __syncwarp();

#pragma unroll 2
    for (int it = 0; it < PXC_/128; ++it) {   // 32 iters, 128 px per iter
        int idx = it*32 + lane;
        float4 s  = Sp[idx];
        float4 tv = Tp[idx];
        int4   l  = Lp[idx];
        float2 v;
        v = bin[l.x*32 + lane]; v.x += s.x; v.y += tv.x; bin[l.x*32 + lane] = v;
        v = bin[l.y*32 + lane]; v.x += s.y; v.y += tv.y; bin[l.y*32 + lane] = v;
        v = bin[l.z*32 + lane]; v.x += s.z; v.y += tv.z; bin[l.z*32 + lane] = v;
        v = bin[l.w*32 + lane]; v.x += s.w; v.y += tv.w; bin[l.w*32 + lane] = v;
    }
    __syncwarp();

    // Reduce 32 lanes per class; shuffle tree.
#pragma unroll
    for (int k = 0; k < K_; ++k) {
        float2 v = bin[k*32 + lane];
#pragma unroll
        for (int off = 16; off; off >>= 1) {
            v.x += __shfl_down_sync(0xffffffff, v.x, off);
            v.y += __shfl_down_sync(0xffffffff, v.y, off);
        }
        if (lane == 0) { outb[warp][0][k] = v.x; outb[warp][1][k] = v.y; }
    }
    __syncwarp();

    // 2*K_ = 38 outputs > 32 lanes: loop.
    for (int i = lane; i < 2*K_; i += 32) {
        int t = i >= K_;
        int k = i - t*K_;
        d_scr[((size_t)((b*NCHUNK_ + chunk)*2 + t)*C_ + c)*K_ + k] = outb[warp][t][k];
    }
}

// ---------------------------------------------------------------------------
// Kernel 2 (fused tail): 4 blocks, one per (b,t).
// Each block: chunk-reduce -> smem centers -> 19x19 Gram -> d_dots.
// Cosine is invariant to the 1/count scaling, so raw sums suffice.
// The LAST block to arrive (atomic counter) computes the final loss and
// resets the counter. No spin; graph-capture safe.
// ---------------------------------------------------------------------------
__global__ __launch_bounds__(256) void tail_kernel(float* __restrict__ out)
{
    __shared__ float cen[C_*K_];   // 9728 floats = 38.9 KB
    __shared__ int   slast;
    __shared__ float red[256];

    int bt = blockIdx.x;           // b*2 + t
    int b  = bt >> 1, t = bt & 1;
    int tid = threadIdx.x;

    for (int i = tid; i < C_*K_; i += 256) {
        float s = 0.f;
#pragma unroll
        for (int ch = 0; ch < NCHUNK_; ++ch)
            s += d_scr[(size_t)((b*NCHUNK_ + ch)*2 + t)*C_*K_ + i];
        cen[i] = s;
    }
    __syncthreads();

    for (int p = tid; p < K_*K_; p += 256) {
        int i = p / K_, j = p % K_;
        float acc = 0.f;
#pragma unroll 8
        for (int c = 0; c < C_; ++c)
            acc += cen[c*K_ + i] * cen[c*K_ + j];
        d_dots[(size_t)bt*K_*K_ + p] = acc;
    }

    // Publish this block's dots, then count arrivals.
    __threadfence();
    __syncthreads();
    if (tid == 0) {
        unsigned r = atomicAdd(&d_ctr, 1u);
        slast = (r == B_*2 - 1);
    }
    __syncthreads();
    if (!slast) return;

    // Last block: all d_dots slabs are globally visible (writers fenced
    // before arriving; our atomicAdd observed their arrivals).
    __threadfence();

    float v = 0.f;
    for (int p = tid; p < B_*K_*K_; p += 256) {
        int j = p % K_; int r = p / K_;
        int i = r % K_; int bb = r / K_;
        const float* dS = d_dots + (size_t)(bb*2 + 0)*K_*K_;
        const float* dT = d_dots + (size_t)(bb*2 + 1)*K_*K_;
        float nSi = fmaxf(sqrtf(dS[i*K_ + i]), 1e-8f);
        float nSj = fmaxf(sqrtf(dS[j*K_ + j]), 1e-8f);
        float pS  = dS[i*K_ + j] / (nSi * nSj);
        float nTi = fmaxf(sqrtf(dT[i*K_ + i]), 1e-8f);
        float nTj = fmaxf(sqrtf(dT[j*K_ + j]), 1e-8f);
        float pT  = dT[i*K_ + j] / (nTi * nTj);
        float df  = pS - pT;
        v += df * df;
    }
    red[tid] = v;
    __syncthreads();
    for (int s = 128; s > 0; s >>= 1) {
        if (tid < s) red[tid] += red[tid + s];
        __syncthreads();
    }
    if (tid == 0) {
        out[0] = red[0] / (float)(B_*K_*K_);
        d_ctr  = 0;   // reset for next call (deterministic)
    }
}

// ---------------------------------------------------------------------------
extern "C" void kernel_launch(void* const* d_in, const int* in_sizes, int n_in,
                              void* d_out, int out_size)
{
    const float* S   = (const float*)d_in[0];   // preds_S [2,512,128,256] f32
    const float* T   = (const float*)d_in[1];   // preds_T [2,512,128,256] f32
    const int*   tgt = (const int*)  d_in[2];   // target  [2,1,128,256] i32
    float* out = (float*)d_out;                 // scalar f32

    seg_kernel<<<B_*NCT_*NCHUNK_, 128>>>(S, T, tgt);   // 2048 blocks
    tail_kernel<<<B_*2, 256>>>(out);
}

// round 6
// speedup vs baseline: 1.2380x; 1.2380x over previous
#include <cuda_runtime.h>
#include <math.h>

// Problem constants
#define B_   2
#define C_   512
#define HW_  32768          // H*W = 128*256
#define K_   19
#define GC_  4              // channels per block (1 per warp)
#define NCT_ (C_/GC_)       // 128 channel tiles
#define NCHUNK_ 8
#define PXC_ (HW_/NCHUNK_)  // 4096 pixels per chunk
#define NIT_ (PXC_/128)     // 32 iterations per block

// Scratch (no cudaMalloc allowed)
__device__ float d_scr[B_*NCHUNK_*2*C_*K_];   // 1.24 MB partial class sums
__device__ float d_dots[B_*2*K_*K_];          // Gram matrices
__device__ unsigned int d_ctr;                // arrival counter (reset each call)

// One S/T float4 pair routed into per-warp float2 bins (bank == f(lane): conflict-free)
#define RMW_(sv, tv, lv)                                                        \
    do {                                                                        \
        float2 v_;                                                              \
        v_ = bin[(lv).x*32 + lane]; v_.x += (sv).x; v_.y += (tv).x; bin[(lv).x*32 + lane] = v_; \
        v_ = bin[(lv).y*32 + lane]; v_.x += (sv).y; v_.y += (tv).y; bin[(lv).y*32 + lane] = v_; \
        v_ = bin[(lv).z*32 + lane]; v_.x += (sv).z; v_.y += (tv).z; bin[(lv).z*32 + lane] = v_; \
        v_ = bin[(lv).w*32 + lane]; v_.x += (sv).w; v_.y += (tv).w; bin[(lv).w*32 + lane] = v_; \
    } while (0)

// ---------------------------------------------------------------------------
// Kernel 1: segment sums, branch-free, software-pipelined.
// lane = pixel, warp = channel. Prefetch next iteration's 3 vector loads into
// registers BEFORE the current bin-RMW chain so DRAM loads stay in flight
// (streaming __ldcs hints: data has zero reuse).
// ---------------------------------------------------------------------------
__global__ __launch_bounds__(128, 8) void seg_kernel(
    const float* __restrict__ S,
    const float* __restrict__ T,
    const int*   __restrict__ tgt)
{
    __shared__ float2 bins[GC_][K_*32];   // 4 warps x 19x32 float2 = 19.5 KB
    __shared__ float  outb[GC_][2][K_];

    int tid  = threadIdx.x;
    int lane = tid & 31;
    int warp = tid >> 5;

    int blk   = blockIdx.x;               // b*1024 + ct*8 + chunk
    int chunk = blk & (NCHUNK_ - 1);
    int ct    = (blk >> 3) & (NCT_ - 1);
    int b     = blk >> 10;
    int c     = ct * GC_ + warp;

    const float4* Sp = (const float4*)(S + ((size_t)(b*C_ + c))*HW_ + chunk*PXC_);
    const float4* Tp = (const float4*)(T + ((size_t)(b*C_ + c))*HW_ + chunk*PXC_);
    const int4*   Lp = (const int4*)(tgt + (size_t)b*HW_ + chunk*PXC_);

    float2* bin = bins[warp];
    for (int i = lane; i < K_*32; i += 32) bin[i] = make_float2(0.f, 0.f);
    __syncwarp();

    // Software pipeline: stage next loads while current RMW chain runs.
    float4 s0 = __ldcs(Sp + lane);
    float4 t0 = __ldcs(Tp + lane);
    int4   l0 = __ldg (Lp + lane);

#pragma unroll 4
    for (int it = 1; it < NIT_; ++it) {
        int idx = it*32 + lane;
        float4 s1 = __ldcs(Sp + idx);
        float4 t1 = __ldcs(Tp + idx);
        int4   l1 = __ldg (Lp + idx);
        RMW_(s0, t0, l0);
        s0 = s1; t0 = t1; l0 = l1;
    }
    RMW_(s0, t0, l0);
    __syncwarp();

    // Reduce 32 lanes per class; shuffle tree.
#pragma unroll
    for (int k = 0; k < K_; ++k) {
        float2 v = bin[k*32 + lane];
#pragma unroll
        for (int off = 16; off; off >>= 1) {
            v.x += __shfl_down_sync(0xffffffff, v.x, off);
            v.y += __shfl_down_sync(0xffffffff, v.y, off);
        }
        if (lane == 0) { outb[warp][0][k] = v.x; outb[warp][1][k] = v.y; }
    }
    __syncwarp();

    for (int i = lane; i < 2*K_; i += 32) {   // 38 outputs > 32 lanes: loop
        int t = i >= K_;
        int k = i - t*K_;
        d_scr[((size_t)((b*NCHUNK_ + chunk)*2 + t)*C_ + c)*K_ + k] = outb[warp][t][k];
    }
}

// ---------------------------------------------------------------------------
// Kernel 2 (fused tail): 4 blocks x 1024 threads, one block per (b,t).
// chunk-reduce -> smem centers -> Gram via warp-per-(i,j) pair with lane-
// parallel channel sums (16 iters + shuffle tree, not 512 serial) -> d_dots.
// Cosine is invariant to the 1/count scaling, so raw sums suffice.
// Last-arriving block computes the loss and resets the counter.
// ---------------------------------------------------------------------------
__global__ __launch_bounds__(1024) void tail_kernel(float* __restrict__ out)
{
    __shared__ float cen[C_*K_];   // 9728 floats = 38.9 KB
    __shared__ float red[32];
    __shared__ int   slast;

    int bt = blockIdx.x;           // b*2 + t
    int b  = bt >> 1, t = bt & 1;
    int tid  = threadIdx.x;
    int lane = tid & 31;
    int warp = tid >> 5;

    // Chunk-reduce partials into centers (1024 threads, ~10 elems each).
    for (int i = tid; i < C_*K_; i += 1024) {
        float s = 0.f;
#pragma unroll
        for (int ch = 0; ch < NCHUNK_; ++ch)
            s += d_scr[(size_t)((b*NCHUNK_ + ch)*2 + t)*C_*K_ + i];
        cen[i] = s;
    }
    __syncthreads();

    // Gram: warp per (i,j) pair, lanes over channels (stride 19*lane -> conflict-free).
    for (int p = warp; p < K_*K_; p += 32) {
        int i = p / K_, j = p % K_;
        float acc = 0.f;
#pragma unroll
        for (int c = lane; c < C_; c += 32)
            acc += cen[c*K_ + i] * cen[c*K_ + j];
#pragma unroll
        for (int off = 16; off; off >>= 1)
            acc += __shfl_down_sync(0xffffffff, acc, off);
        if (lane == 0) d_dots[(size_t)bt*K_*K_ + p] = acc;
    }

    // Publish dots, count arrivals.
    __threadfence();
    __syncthreads();
    if (tid == 0) {
        unsigned r = atomicAdd(&d_ctr, 1u);
        slast = (r == B_*2 - 1);
    }
    __syncthreads();
    if (!slast) return;
    __threadfence();

    // Loss over 722 (b,i,j) entries; 1024-thread reduction.
    float v = 0.f;
    if (tid < B_*K_*K_) {
        int j = tid % K_; int r = tid / K_;
        int i = r % K_;   int bb = r / K_;
        const float* dS = d_dots + (size_t)(bb*2 + 0)*K_*K_;
        const float* dT = d_dots + (size_t)(bb*2 + 1)*K_*K_;
        float nSi = fmaxf(sqrtf(dS[i*K_ + i]), 1e-8f);
        float nSj = fmaxf(sqrtf(dS[j*K_ + j]), 1e-8f);
        float pS  = dS[i*K_ + j] / (nSi * nSj);
        float nTi = fmaxf(sqrtf(dT[i*K_ + i]), 1e-8f);
        float nTj = fmaxf(sqrtf(dT[j*K_ + j]), 1e-8f);
        float pT  = dT[i*K_ + j] / (nTi * nTj);
        float df  = pS - pT;
        v = df * df;
    }
#pragma unroll
    for (int off = 16; off; off >>= 1)
        v += __shfl_down_sync(0xffffffff, v, off);
    if (lane == 0) red[warp] = v;
    __syncthreads();
    if (warp == 0) {
        float s = red[lane];
#pragma unroll
        for (int off = 16; off; off >>= 1)
            s += __shfl_down_sync(0xffffffff, s, off);
        if (lane == 0) {
            out[0] = s / (float)(B_*K_*K_);
            d_ctr  = 0;   // reset for next call
        }
    }
}

// ---------------------------------------------------------------------------
extern "C" void kernel_launch(void* const* d_in, const int* in_sizes, int n_in,
                              void* d_out, int out_size)
{
    const float* S   = (const float*)d_in[0];   // preds_S [2,512,128,256] f32
    const float* T   = (const float*)d_in[1];   // preds_T [2,512,128,256] f32
    const int*   tgt = (const int*)  d_in[2];   // target  [2,1,128,256] i32
    float* out = (float*)d_out;                 // scalar f32

    seg_kernel<<<B_*NCT_*NCHUNK_, 128>>>(S, T, tgt);   // 2048 blocks
    tail_kernel<<<B_*2, 1024>>>(out);
}